// round 16
// baseline (speedup 1.0000x reference)
#include <cuda_runtime.h>
#include <math.h>
#include <stdint.h>

#define B_  4
#define L_  2048
#define D_  768
#define H_  12
#define HD_ 64
#define M_  (B_*L_)

// ---------------------------------------------------------------------------
// Scratch (device globals; all values tf32-rounded fp32)
// K is stored with kv-rows permuted within 8-groups (rho: j<4 -> 2j, else
// 2j-7) so that S-accumulator fragments are directly PV A-fragments.
// ---------------------------------------------------------------------------
__device__ float g_q [(size_t)M_*D_];    // [B,H,L,hd], pre-scaled 1/8
__device__ float g_k [(size_t)M_*D_];    // [B,H,rho(L),hd]  (row-permuted!)
__device__ float g_vt[(size_t)M_*D_];    // [B,H,hd,L]       (transposed)
__device__ float g_o [(size_t)M_*D_];    // [M,D] attention output
__device__ float g_wt[4][(size_t)D_*D_]; // W^T rounded (q,k,v,o)

// ---------------------------------------------------------------------------
// Baseline-PTX helpers (sm_80-era: valid at target sm_103)
// ---------------------------------------------------------------------------
__device__ __forceinline__ uint32_t smem_to_u32(const void* p) {
    uint32_t a;
    asm("{ .reg .u64 t; cvta.to.shared.u64 t, %1; cvt.u32.u64 %0, t; }"
        : "=r"(a) : "l"(p));
    return a;
}
__device__ __forceinline__ void ldsm_x4(uint32_t addr, uint32_t* r) {
    asm volatile("ldmatrix.sync.aligned.m8n8.x4.shared.b16 {%0,%1,%2,%3}, [%4];"
                 : "=r"(r[0]), "=r"(r[1]), "=r"(r[2]), "=r"(r[3]) : "r"(addr));
}
__device__ __forceinline__ void mma_tf32(float* c, const uint32_t* a,
                                         const uint32_t b0, const uint32_t b1) {
    asm volatile("mma.sync.aligned.m16n8k8.row.col.f32.tf32.tf32.f32 "
                 "{%0,%1,%2,%3}, {%4,%5,%6,%7}, {%8,%9}, {%0,%1,%2,%3};"
                 : "+f"(c[0]), "+f"(c[1]), "+f"(c[2]), "+f"(c[3])
                 : "r"(a[0]), "r"(a[1]), "r"(a[2]), "r"(a[3]), "r"(b0), "r"(b1));
}
__device__ __forceinline__ float rna(float x) {
    uint32_t u;
    asm("cvt.rna.tf32.f32 %0, %1;" : "=r"(u) : "f"(x));
    return __uint_as_float(u);
}
__device__ __forceinline__ uint32_t rna_u(uint32_t x) {
    uint32_t u;
    float f = __uint_as_float(x);
    asm("cvt.rna.tf32.f32 %0, %1;" : "=r"(u) : "f"(f));
    return u;
}
__device__ __forceinline__ float trunc_tf32(float x) {
    return __uint_as_float(__float_as_uint(x) & 0xFFFFE000u);
}
#define CP_ASYNC16(saddr, gptr) \
    asm volatile("cp.async.cg.shared.global [%0], [%1], 16;" \
                 :: "r"(saddr), "l"(gptr))
#define CP_COMMIT()  asm volatile("cp.async.commit_group;" ::: "memory")
#define CP_WAIT(N)   asm volatile("cp.async.wait_group %0;" :: "n"(N) : "memory")

// 256B-row swizzle: XOR 16B-chunk bits [4:7) with row bits [0:3)
#define SW256(row, cb) ((uint32_t)((row) * 256 + ((cb) ^ (((row) & 7) << 4))))
// 128B-row swizzle
#define SW128R(row, cb) ((uint32_t)((row) * 128 + ((cb) ^ (((row) & 7) << 4))))

// kv permutation within 8-groups: logical l -> physical position
__device__ __forceinline__ int rho_kv(int l) {
    const int j = l & 7;
    return (l & ~7) | ((j < 4) ? (2 * j) : (2 * j - 7));
}

// ---------------------------------------------------------------------------
// Preprocessing: transpose + tf32-round weights
// ---------------------------------------------------------------------------
__global__ __launch_bounds__(256)
void pre_w(const float* __restrict__ W0, const float* __restrict__ W1,
           const float* __restrict__ W2, const float* __restrict__ W3,
           float* __restrict__ wt)
{
    __shared__ float t[32][33];
    const int w = blockIdx.z;
    const float* W = (w == 0) ? W0 : (w == 1) ? W1 : (w == 2) ? W2 : W3;
    float* WT = wt + (size_t)w * D_ * D_;
    const int tx = threadIdx.x & 31, ty = threadIdx.x >> 5;   // 32 x 8
    const int x0 = blockIdx.x * 32, y0 = blockIdx.y * 32;
#pragma unroll
    for (int i = 0; i < 32; i += 8)
        t[ty + i][tx] = W[(size_t)(y0 + ty + i) * D_ + x0 + tx];
    __syncthreads();
#pragma unroll
    for (int i = 0; i < 32; i += 8)
        WT[(size_t)(x0 + ty + i) * D_ + y0 + tx] = rna(t[tx][ty + i]);
}

// ---------------------------------------------------------------------------
// GEMM mainloop: 128x128 tile, 8 warps (2m x 4n), K-chunks of 32 floats
// (128B rows), 3-stage ring, ONE sync per chunk, 2 CTAs/SM.
// ---------------------------------------------------------------------------
#define GO_OFFB  16384
#define GO_SSZ   32768
#define G_DYN    (3 * GO_SSZ + 1024)

template<bool RNA_A>
__device__ __forceinline__
void gemm_main128(const float* __restrict__ A, const float* __restrict__ Bt,
                  int m0, int n0, uint32_t base, float acc[4][4][4])
{
    const int tid  = threadIdx.x;
    const int wid  = tid >> 5;
    const int lane = tid & 31;
    const int wm   = wid & 1;
    const int wn   = wid >> 1;

    const int lr = tid >> 1;
    const int lc0 = (tid & 1) * 64;
    const float* gA = A  + (size_t)(m0 + lr) * D_ + (lc0 >> 2);
    const float* gB = Bt + (size_t)(n0 + lr) * D_ + (lc0 >> 2);

    const int arow = wm * 64 + (lane & 7) + ((lane >> 3) & 1) * 8;
    const int acb  = (lane >> 4) * 16;
    const int brow = wn * 32 + (lane & 7) + ((lane >> 4) & 1) * 8;
    const int bcb  = ((lane >> 3) & 1) * 16;

#pragma unroll
    for (int mi = 0; mi < 4; mi++)
#pragma unroll
        for (int nt = 0; nt < 4; nt++)
#pragma unroll
            for (int c = 0; c < 4; c++) acc[mi][nt][c] = 0.0f;

    const int NCHUNK = D_ / 32;   // 24
    auto load_chunk = [&](int kc, int stg) {
        const uint32_t sb = base + (uint32_t)stg * GO_SSZ;
        const int kf = kc * 32;
#pragma unroll
        for (int c = 0; c < 4; c++) {
            const uint32_t so = SW128R(lr, lc0 + c * 16);
            CP_ASYNC16(sb + so,           gA + kf + c * 4);
            CP_ASYNC16(sb + GO_OFFB + so, gB + kf + c * 4);
        }
    };

    load_chunk(0, 0); CP_COMMIT();
    load_chunk(1, 1); CP_COMMIT();
    CP_WAIT(1);
    __syncthreads();

    int scomp = 0;
    for (int i = 0; i < NCHUNK; i++) {
        const uint32_t sb = base + (uint32_t)scomp * GO_SSZ;
#pragma unroll
        for (int ks = 0; ks < 4; ks++) {
            uint32_t a[4][4], bf[2][4];
#pragma unroll
            for (int mi = 0; mi < 4; mi++) {
                ldsm_x4(sb + SW128R(arow + mi * 16, acb + ks * 32), a[mi]);
                if (RNA_A) {
#pragma unroll
                    for (int j = 0; j < 4; j++) a[mi][j] = rna_u(a[mi][j]);
                }
            }
#pragma unroll
            for (int nbh = 0; nbh < 2; nbh++)
                ldsm_x4(sb + GO_OFFB + SW128R(brow + nbh * 16, bcb + ks * 32), bf[nbh]);
#pragma unroll
            for (int mi = 0; mi < 4; mi++)
#pragma unroll
                for (int nt = 0; nt < 4; nt++)
                    mma_tf32(acc[mi][nt], a[mi],
                             bf[nt >> 1][(nt & 1) * 2], bf[nt >> 1][(nt & 1) * 2 + 1]);
        }
        if (i + 2 < NCHUNK) {
            int snext = scomp + 2; if (snext >= 3) snext -= 3;
            load_chunk(i + 2, snext);
            CP_COMMIT();
        }
        if (i + 1 < NCHUNK) {
            if (i + 2 < NCHUNK) { CP_WAIT(1); } else { CP_WAIT(0); }
            __syncthreads();
        }
        if (++scomp == 3) scomp = 0;
    }
}

// Fused QKV projection: blockIdx.z selects {Wq->q, Wk->k (kv-permuted), Wv->vt}.
__global__ __launch_bounds__(256, 2)
void qkv_gemm(const float* __restrict__ A, const float* __restrict__ wt,
              const float* __restrict__ bq, const float* __restrict__ bk,
              const float* __restrict__ bv,
              float* __restrict__ Oq, float* __restrict__ Ok,
              float* __restrict__ Ovt)
{
    extern __shared__ char dsm[];
    const uint32_t raw  = smem_to_u32(dsm);
    const uint32_t base = (raw + 1023) & ~1023u;

    const int z = blockIdx.z;
    const float* Bt   = wt + (size_t)z * D_ * D_;
    const float* bias = (z == 0) ? bq : (z == 1) ? bk : bv;
    const float scale = (z == 0) ? 0.125f : 1.0f;
    float* Chl = (z == 0) ? Oq : Ok;

    const int m0 = blockIdx.y * 128;
    const int n0 = blockIdx.x * 128;

    float acc[4][4][4];
    gemm_main128<true>(A, Bt, m0, n0, base, acc);

    const int lane = threadIdx.x & 31;
    const int wid  = threadIdx.x >> 5;
    const int wm = wid & 1, wn = wid >> 1;
    const int grp = lane >> 2;
    const int tig = lane & 3;
#pragma unroll
    for (int nt = 0; nt < 4; nt++) {
        const int col = n0 + wn * 32 + nt * 8 + tig * 2;
        const float b0 = bias[col], b1 = bias[col + 1];
#pragma unroll
        for (int mi = 0; mi < 4; mi++)
#pragma unroll
            for (int half = 0; half < 2; half++) {
                const int m = m0 + wm * 64 + mi * 16 + grp + half * 8;
                const float v0 = (acc[mi][nt][half * 2 + 0] + b0) * scale;
                const float v1 = (acc[mi][nt][half * 2 + 1] + b1) * scale;
                const int batch = m / L_;
                int lrow = m % L_;
                const int h = col / HD_, d0 = col % HD_;
                if (z < 2) {
                    if (z == 1) lrow = rho_kv(lrow);   // K: bake kv permutation
                    float2 v; v.x = rna(v0); v.y = rna(v1);
                    *(float2*)(Chl + (((size_t)(batch * H_ + h) * L_ + lrow) * HD_ + d0)) = v;
                } else {
                    const size_t vb = ((size_t)(batch * H_ + h) * HD_ + d0) * L_ + lrow;
                    Ovt[vb]      = rna(v0);
                    Ovt[vb + L_] = rna(v1);
                }
            }
    }
}

// Output projection (same mainloop, fp32 [M,D] epilogue).
__global__ __launch_bounds__(256, 2)
void out_gemm(const float* __restrict__ A, const float* __restrict__ Bt,
              const float* __restrict__ bias, float* __restrict__ C)
{
    extern __shared__ char dsm[];
    const uint32_t raw  = smem_to_u32(dsm);
    const uint32_t base = (raw + 1023) & ~1023u;
    const int m0 = blockIdx.y * 128;
    const int n0 = blockIdx.x * 128;

    float acc[4][4][4];
    gemm_main128<false>(A, Bt, m0, n0, base, acc);

    const int lane = threadIdx.x & 31;
    const int wid  = threadIdx.x >> 5;
    const int wm = wid & 1, wn = wid >> 1;
    const int grp = lane >> 2;
    const int tig = lane & 3;
#pragma unroll
    for (int nt = 0; nt < 4; nt++) {
        const int col = n0 + wn * 32 + nt * 8 + tig * 2;
        const float b0 = bias[col], b1 = bias[col + 1];
#pragma unroll
        for (int mi = 0; mi < 4; mi++)
#pragma unroll
            for (int half = 0; half < 2; half++) {
                const int m = m0 + wm * 64 + mi * 16 + grp + half * 8;
                float2 v;
                v.x = acc[mi][nt][half * 2 + 0] + b0;
                v.y = acc[mi][nt][half * 2 + 1] + b1;
                *(float2*)(C + (size_t)m * D_ + col) = v;
            }
    }
}

// ---------------------------------------------------------------------------
// tf32 flash attention, 2 CTAs/SM: CTA = 128 q-rows, 4 warps (128 thr),
// warp tile 32q x 64kv. Q fragments REGISTER-RESIDENT (staged once through
// stage2's buffer, then freed). smem = 3 x 32KB stages only -> 2 CTAs/SM
// cover each other's sync/drain bubbles. 3-stage ring, ONE sync/iter.
// exp interleaved with PV per kc (shorter serial drain). NO P round-trip:
// K kv-permuted so S fragments (order c0,c2,c1,c3) ARE PV A-fragments.
// ---------------------------------------------------------------------------
#define AT_SSZ  32768
#define AT_VOFF 16384
#define AT_DYN  (3 * AT_SSZ + 1024)   // 99328 -> 2 CTAs/SM

__global__ __launch_bounds__(128, 2)
void attn_tf32(const float* __restrict__ Q, const float* __restrict__ K,
               const float* __restrict__ VT, float* __restrict__ O)
{
    extern __shared__ char dsm[];
    const uint32_t raw  = smem_to_u32(dsm);
    const uint32_t base = (raw + 1023) & ~1023u;

    const int tid = threadIdx.x;
    const int wid = tid >> 5;
    const int lane = tid & 31;
    const int b = blockIdx.z, h = blockIdx.y;
    const int q0 = blockIdx.x * 128;
    const size_t hoff = (size_t)(b * H_ + h) * L_ * HD_;

    // Q staged through stage2's buffer: 128 rows x 256B, 1 row/thread
    {
        const float* g = Q + hoff + (size_t)(q0 + tid) * HD_;
        const uint32_t qb = base + 2 * AT_SSZ;
#pragma unroll
        for (int c = 0; c < 16; c++)
            CP_ASYNC16(qb + SW256(tid, c * 16), g + c * 4);
    }
    CP_COMMIT();   // g0: Q

    const int sr = tid >> 1, scb0 = (tid & 1) * 128;   // 128 thr: 2/row
    auto load_stage = [&](int kt, int stg) {
        const uint32_t sb = base + (uint32_t)stg * AT_SSZ;
        const float* gk = K  + hoff + (size_t)(kt + sr) * HD_ + (scb0 >> 2);
        const float* gv = VT + hoff + (size_t)sr * L_ + kt + (scb0 >> 2);
#pragma unroll
        for (int c = 0; c < 8; c++) {
            const uint32_t so = SW256(sr, scb0 + c * 16);
            CP_ASYNC16(sb + so,           gk + c * 4);
            CP_ASYNC16(sb + AT_VOFF + so, gv + c * 4);
        }
    };
    load_stage(0, 0);  CP_COMMIT();   // g1: stage0
    load_stage(64, 1); CP_COMMIT();   // g2: stage1

    const int ar = (lane & 7) + ((lane >> 3) & 1) * 8;   // A-pattern row
    const int ac = (lane >> 4) * 16;                     // A-pattern col byte
    const int br = (lane & 7) + ((lane >> 4) & 1) * 8;   // B-pattern row
    const int bc = ((lane >> 3) & 1) * 16;               // B-pattern col byte

    // Q fragments -> registers (2 qi x 8 ks x 4 = 64 regs)
    CP_WAIT(2);          // Q resident (g1,g2 may be pending)
    __syncthreads();
    uint32_t qf[2][8][4];
    {
        const uint32_t qb = base + 2 * AT_SSZ;
        const uint32_t qrow0 = (uint32_t)(wid * 32);
#pragma unroll
        for (int qi = 0; qi < 2; qi++)
#pragma unroll
            for (int ks = 0; ks < 8; ks++)
                ldsm_x4(qb + SW256(qrow0 + qi * 16 + ar, ks * 32 + ac), qf[qi][ks]);
    }
    __syncthreads();     // all warps done reading stage2 before it's reused
    CP_WAIT(1);          // stage0 resident
    __syncthreads();

    float oacc[2][8][4];
#pragma unroll
    for (int qi = 0; qi < 2; qi++)
#pragma unroll
        for (int nt = 0; nt < 8; nt++)
#pragma unroll
            for (int c = 0; c < 4; c++) oacc[qi][nt][c] = 0.0f;
    float lsum[2][2] = {{0.0f, 0.0f}, {0.0f, 0.0f}};

    const int NIT = L_ / 64;   // 32
    int scomp = 0;
    for (int it = 0; it < NIT; it++) {
        const uint32_t sb = base + (uint32_t)scomp * AT_SSZ;

        // ---- S = Q K^T (K kv-permuted) ----
        float sacc[2][8][4];
#pragma unroll
        for (int qi = 0; qi < 2; qi++)
#pragma unroll
            for (int nt = 0; nt < 8; nt++)
#pragma unroll
                for (int c = 0; c < 4; c++) sacc[qi][nt][c] = 0.0f;
#pragma unroll
        for (int ks = 0; ks < 8; ks++) {
            uint32_t kf[4][4];
#pragma unroll
            for (int nbh = 0; nbh < 4; nbh++)
                ldsm_x4(sb + SW256(nbh * 16 + br, ks * 32 + bc), kf[nbh]);
#pragma unroll
            for (int qi = 0; qi < 2; qi++)
#pragma unroll
                for (int nt = 0; nt < 8; nt++)
                    mma_tf32(sacc[qi][nt], qf[qi][ks],
                             kf[nt >> 1][(nt & 1) * 2], kf[nt >> 1][(nt & 1) * 2 + 1]);
        }

        // ---- per kc: exp 8 values, then that kc's PV MMAs (interleaved) ----
#pragma unroll
        for (int kc = 0; kc < 8; kc++) {
            uint32_t vf[4][4];
#pragma unroll
            for (int nbh = 0; nbh < 4; nbh++)
                ldsm_x4(sb + AT_VOFF + SW256(nbh * 16 + br, kc * 32 + bc), vf[nbh]);
#pragma unroll
            for (int qi = 0; qi < 2; qi++) {
                const float t0 = trunc_tf32(__expf(sacc[qi][kc][0]));
                const float t1 = trunc_tf32(__expf(sacc[qi][kc][1]));
                const float t2 = trunc_tf32(__expf(sacc[qi][kc][2]));
                const float t3 = trunc_tf32(__expf(sacc[qi][kc][3]));
                lsum[qi][0] += t0 + t1;
                lsum[qi][1] += t2 + t3;
                const uint32_t pa[4] = {
                    __float_as_uint(t0), __float_as_uint(t2),
                    __float_as_uint(t1), __float_as_uint(t3) };
#pragma unroll
                for (int nt = 0; nt < 8; nt++)
                    mma_tf32(oacc[qi][nt], pa,
                             vf[nt >> 1][(nt & 1) * 2], vf[nt >> 1][(nt & 1) * 2 + 1]);
            }
        }

        // ---- pipeline: prefetch it+2 into (scomp+2)%3; wait for it+1 ----
        if (it + 2 < NIT) {
            int snext = scomp + 2; if (snext >= 3) snext -= 3;
            load_stage((it + 2) * 64, snext);
            CP_COMMIT();
        }
        if (it + 1 < NIT) {
            if (it + 2 < NIT) { CP_WAIT(1); } else { CP_WAIT(0); }
            __syncthreads();
        }
        if (++scomp == 3) scomp = 0;
    }

    // ---- epilogue ----
#pragma unroll
    for (int qi = 0; qi < 2; qi++)
#pragma unroll
        for (int hf = 0; hf < 2; hf++) {
            float s = lsum[qi][hf];
            s += __shfl_xor_sync(0xffffffffu, s, 1);
            s += __shfl_xor_sync(0xffffffffu, s, 2);
            lsum[qi][hf] = 1.0f / s;
        }

#pragma unroll
    for (int qi = 0; qi < 2; qi++) {
        const size_t row0 = (size_t)b * L_ + q0 + wid * 32 + qi * 16 + (lane >> 2);
        const size_t row1 = row0 + 8;
        const float inv0 = lsum[qi][0];
        const float inv1 = lsum[qi][1];
#pragma unroll
        for (int nt = 0; nt < 8; nt++) {
            const int col = h * HD_ + nt * 8 + (lane & 3) * 2;
            float2 v0; v0.x = rna(oacc[qi][nt][0] * inv0); v0.y = rna(oacc[qi][nt][1] * inv0);
            float2 v1; v1.x = rna(oacc[qi][nt][2] * inv1); v1.y = rna(oacc[qi][nt][3] * inv1);
            *(float2*)(O + row0 * D_ + col) = v0;
            *(float2*)(O + row1 * D_ + col) = v1;
        }
    }
}

// ---------------------------------------------------------------------------
extern "C" void kernel_launch(void* const* d_in, const int* in_sizes, int n_in,
                              void* d_out, int out_size)
{
    const float* x  = (const float*)d_in[0];
    const float* Wq = (const float*)d_in[1];
    const float* bq = (const float*)d_in[2];
    const float* Wk = (const float*)d_in[3];
    const float* bk = (const float*)d_in[4];
    const float* Wv = (const float*)d_in[5];
    const float* bv = (const float*)d_in[6];
    const float* Wo = (const float*)d_in[7];
    const float* bo = (const float*)d_in[8];
    float* out = (float*)d_out;

    float *q, *k, *vt, *o, *wt;
    cudaGetSymbolAddress((void**)&q,  g_q);
    cudaGetSymbolAddress((void**)&k,  g_k);
    cudaGetSymbolAddress((void**)&vt, g_vt);
    cudaGetSymbolAddress((void**)&o,  g_o);
    cudaGetSymbolAddress((void**)&wt, g_wt);
    const size_t WSZ = (size_t)D_ * D_;

    cudaFuncSetAttribute(qkv_gemm,  cudaFuncAttributeMaxDynamicSharedMemorySize, G_DYN);
    cudaFuncSetAttribute(out_gemm,  cudaFuncAttributeMaxDynamicSharedMemorySize, G_DYN);
    cudaFuncSetAttribute(attn_tf32, cudaFuncAttributeMaxDynamicSharedMemorySize, AT_DYN);

    // 1. weight transpose + round
    pre_w<<<dim3(D_ / 32, D_ / 32, 4), 256>>>(Wq, Wk, Wv, Wo, wt);

    // 2. fused QKV projections (128x128 tiles, K32, 3-stage, 2 CTAs/SM)
    qkv_gemm<<<dim3(D_ / 128, M_ / 128, 3), 256, G_DYN>>>(
        x, wt, bq, bk, bv, q, k, vt);

    // 3. attention (128q CTAs, 2 CTAs/SM, Q in registers, exp/PV interleaved)
    attn_tf32<<<dim3(L_ / 128, H_, B_), 128, AT_DYN>>>(q, k, vt, o);

    // 4. output projection (K32, 3-stage, 2 CTAs/SM)
    out_gemm<<<dim3(D_ / 128, M_ / 128), 256, G_DYN>>>(o, wt + 3 * WSZ, bo, out);
}

// round 17
// speedup vs baseline: 1.7945x; 1.7945x over previous
#include <cuda_runtime.h>
#include <math.h>
#include <stdint.h>

#define B_  4
#define L_  2048
#define D_  768
#define H_  12
#define HD_ 64
#define M_  (B_*L_)

// ---------------------------------------------------------------------------
// Scratch (device globals; all values tf32-rounded fp32)
// K is stored with kv-rows permuted within 8-groups (rho: j<4 -> 2j, else
// 2j-7) so that S-accumulator fragments are directly PV A-fragments.
// ---------------------------------------------------------------------------
__device__ float g_q [(size_t)M_*D_];    // [B,H,L,hd], pre-scaled 1/8
__device__ float g_k [(size_t)M_*D_];    // [B,H,rho(L),hd]  (row-permuted!)
__device__ float g_vt[(size_t)M_*D_];    // [B,H,hd,L]       (transposed)
__device__ float g_o [(size_t)M_*D_];    // [M,D] attention output
__device__ float g_wt[4][(size_t)D_*D_]; // W^T rounded (q,k,v,o)

// ---------------------------------------------------------------------------
// Baseline-PTX helpers (sm_80-era: valid at target sm_103)
// ---------------------------------------------------------------------------
__device__ __forceinline__ uint32_t smem_to_u32(const void* p) {
    uint32_t a;
    asm("{ .reg .u64 t; cvta.to.shared.u64 t, %1; cvt.u32.u64 %0, t; }"
        : "=r"(a) : "l"(p));
    return a;
}
__device__ __forceinline__ void ldsm_x4(uint32_t addr, uint32_t* r) {
    asm volatile("ldmatrix.sync.aligned.m8n8.x4.shared.b16 {%0,%1,%2,%3}, [%4];"
                 : "=r"(r[0]), "=r"(r[1]), "=r"(r[2]), "=r"(r[3]) : "r"(addr));
}
__device__ __forceinline__ void mma_tf32(float* c, const uint32_t* a,
                                         const uint32_t b0, const uint32_t b1) {
    asm volatile("mma.sync.aligned.m16n8k8.row.col.f32.tf32.tf32.f32 "
                 "{%0,%1,%2,%3}, {%4,%5,%6,%7}, {%8,%9}, {%0,%1,%2,%3};"
                 : "+f"(c[0]), "+f"(c[1]), "+f"(c[2]), "+f"(c[3])
                 : "r"(a[0]), "r"(a[1]), "r"(a[2]), "r"(a[3]), "r"(b0), "r"(b1));
}
__device__ __forceinline__ float rna(float x) {
    uint32_t u;
    asm("cvt.rna.tf32.f32 %0, %1;" : "=r"(u) : "f"(x));
    return __uint_as_float(u);
}
__device__ __forceinline__ uint32_t rna_u(uint32_t x) {
    uint32_t u;
    float f = __uint_as_float(x);
    asm("cvt.rna.tf32.f32 %0, %1;" : "=r"(u) : "f"(f));
    return u;
}
__device__ __forceinline__ float trunc_tf32(float x) {
    return __uint_as_float(__float_as_uint(x) & 0xFFFFE000u);
}
#define CP_ASYNC16(saddr, gptr) \
    asm volatile("cp.async.cg.shared.global [%0], [%1], 16;" \
                 :: "r"(saddr), "l"(gptr))
#define CP_COMMIT()  asm volatile("cp.async.commit_group;" ::: "memory")
#define CP_WAIT(N)   asm volatile("cp.async.wait_group %0;" :: "n"(N) : "memory")

// 256B-row swizzle: XOR 16B-chunk bits [4:7) with row bits [0:3)
#define SW256(row, cb) ((uint32_t)((row) * 256 + ((cb) ^ (((row) & 7) << 4))))
// 128B-row swizzle
#define SW128R(row, cb) ((uint32_t)((row) * 128 + ((cb) ^ (((row) & 7) << 4))))

// kv permutation within 8-groups: logical l -> physical position
__device__ __forceinline__ int rho_kv(int l) {
    const int j = l & 7;
    return (l & ~7) | ((j < 4) ? (2 * j) : (2 * j - 7));
}

// ---------------------------------------------------------------------------
// Preprocessing: transpose + tf32-round weights
// ---------------------------------------------------------------------------
__global__ __launch_bounds__(256)
void pre_w(const float* __restrict__ W0, const float* __restrict__ W1,
           const float* __restrict__ W2, const float* __restrict__ W3,
           float* __restrict__ wt)
{
    __shared__ float t[32][33];
    const int w = blockIdx.z;
    const float* W = (w == 0) ? W0 : (w == 1) ? W1 : (w == 2) ? W2 : W3;
    float* WT = wt + (size_t)w * D_ * D_;
    const int tx = threadIdx.x & 31, ty = threadIdx.x >> 5;   // 32 x 8
    const int x0 = blockIdx.x * 32, y0 = blockIdx.y * 32;
#pragma unroll
    for (int i = 0; i < 32; i += 8)
        t[ty + i][tx] = W[(size_t)(y0 + ty + i) * D_ + x0 + tx];
    __syncthreads();
#pragma unroll
    for (int i = 0; i < 32; i += 8)
        WT[(size_t)(x0 + ty + i) * D_ + y0 + tx] = rna(t[tx][ty + i]);
}

// ---------------------------------------------------------------------------
// GEMM mainloop: 128x128 tile, 8 warps (2m x 4n), K-chunks of 32 floats
// (128B rows), 3-stage ring, ONE sync per chunk, 2 CTAs/SM.
// ---------------------------------------------------------------------------
#define GO_OFFB  16384
#define GO_SSZ   32768
#define G_DYN    (3 * GO_SSZ + 1024)

template<bool RNA_A>
__device__ __forceinline__
void gemm_main128(const float* __restrict__ A, const float* __restrict__ Bt,
                  int m0, int n0, uint32_t base, float acc[4][4][4])
{
    const int tid  = threadIdx.x;
    const int wid  = tid >> 5;
    const int lane = tid & 31;
    const int wm   = wid & 1;
    const int wn   = wid >> 1;

    const int lr = tid >> 1;
    const int lc0 = (tid & 1) * 64;
    const float* gA = A  + (size_t)(m0 + lr) * D_ + (lc0 >> 2);
    const float* gB = Bt + (size_t)(n0 + lr) * D_ + (lc0 >> 2);

    const int arow = wm * 64 + (lane & 7) + ((lane >> 3) & 1) * 8;
    const int acb  = (lane >> 4) * 16;
    const int brow = wn * 32 + (lane & 7) + ((lane >> 4) & 1) * 8;
    const int bcb  = ((lane >> 3) & 1) * 16;

#pragma unroll
    for (int mi = 0; mi < 4; mi++)
#pragma unroll
        for (int nt = 0; nt < 4; nt++)
#pragma unroll
            for (int c = 0; c < 4; c++) acc[mi][nt][c] = 0.0f;

    const int NCHUNK = D_ / 32;   // 24
    auto load_chunk = [&](int kc, int stg) {
        const uint32_t sb = base + (uint32_t)stg * GO_SSZ;
        const int kf = kc * 32;
#pragma unroll
        for (int c = 0; c < 4; c++) {
            const uint32_t so = SW128R(lr, lc0 + c * 16);
            CP_ASYNC16(sb + so,           gA + kf + c * 4);
            CP_ASYNC16(sb + GO_OFFB + so, gB + kf + c * 4);
        }
    };

    load_chunk(0, 0); CP_COMMIT();
    load_chunk(1, 1); CP_COMMIT();
    CP_WAIT(1);
    __syncthreads();

    int scomp = 0;
    for (int i = 0; i < NCHUNK; i++) {
        const uint32_t sb = base + (uint32_t)scomp * GO_SSZ;
#pragma unroll
        for (int ks = 0; ks < 4; ks++) {
            uint32_t a[4][4], bf[2][4];
#pragma unroll
            for (int mi = 0; mi < 4; mi++) {
                ldsm_x4(sb + SW128R(arow + mi * 16, acb + ks * 32), a[mi]);
                if (RNA_A) {
#pragma unroll
                    for (int j = 0; j < 4; j++) a[mi][j] = rna_u(a[mi][j]);
                }
            }
#pragma unroll
            for (int nbh = 0; nbh < 2; nbh++)
                ldsm_x4(sb + GO_OFFB + SW128R(brow + nbh * 16, bcb + ks * 32), bf[nbh]);
#pragma unroll
            for (int mi = 0; mi < 4; mi++)
#pragma unroll
                for (int nt = 0; nt < 4; nt++)
                    mma_tf32(acc[mi][nt], a[mi],
                             bf[nt >> 1][(nt & 1) * 2], bf[nt >> 1][(nt & 1) * 2 + 1]);
        }
        if (i + 2 < NCHUNK) {
            int snext = scomp + 2; if (snext >= 3) snext -= 3;
            load_chunk(i + 2, snext);
            CP_COMMIT();
        }
        if (i + 1 < NCHUNK) {
            if (i + 2 < NCHUNK) { CP_WAIT(1); } else { CP_WAIT(0); }
            __syncthreads();
        }
        if (++scomp == 3) scomp = 0;
    }
}

// Fused QKV projection: blockIdx.z selects {Wq->q, Wk->k (kv-permuted), Wv->vt}.
__global__ __launch_bounds__(256, 2)
void qkv_gemm(const float* __restrict__ A, const float* __restrict__ wt,
              const float* __restrict__ bq, const float* __restrict__ bk,
              const float* __restrict__ bv,
              float* __restrict__ Oq, float* __restrict__ Ok,
              float* __restrict__ Ovt)
{
    extern __shared__ char dsm[];
    const uint32_t raw  = smem_to_u32(dsm);
    const uint32_t base = (raw + 1023) & ~1023u;

    const int z = blockIdx.z;
    const float* Bt   = wt + (size_t)z * D_ * D_;
    const float* bias = (z == 0) ? bq : (z == 1) ? bk : bv;
    const float scale = (z == 0) ? 0.125f : 1.0f;
    float* Chl = (z == 0) ? Oq : Ok;

    const int m0 = blockIdx.y * 128;
    const int n0 = blockIdx.x * 128;

    float acc[4][4][4];
    gemm_main128<true>(A, Bt, m0, n0, base, acc);

    const int lane = threadIdx.x & 31;
    const int wid  = threadIdx.x >> 5;
    const int wm = wid & 1, wn = wid >> 1;
    const int grp = lane >> 2;
    const int tig = lane & 3;
#pragma unroll
    for (int nt = 0; nt < 4; nt++) {
        const int col = n0 + wn * 32 + nt * 8 + tig * 2;
        const float b0 = bias[col], b1 = bias[col + 1];
#pragma unroll
        for (int mi = 0; mi < 4; mi++)
#pragma unroll
            for (int half = 0; half < 2; half++) {
                const int m = m0 + wm * 64 + mi * 16 + grp + half * 8;
                const float v0 = (acc[mi][nt][half * 2 + 0] + b0) * scale;
                const float v1 = (acc[mi][nt][half * 2 + 1] + b1) * scale;
                const int batch = m / L_;
                int lrow = m % L_;
                const int h = col / HD_, d0 = col % HD_;
                if (z < 2) {
                    if (z == 1) lrow = rho_kv(lrow);   // K: bake kv permutation
                    float2 v; v.x = rna(v0); v.y = rna(v1);
                    *(float2*)(Chl + (((size_t)(batch * H_ + h) * L_ + lrow) * HD_ + d0)) = v;
                } else {
                    const size_t vb = ((size_t)(batch * H_ + h) * HD_ + d0) * L_ + lrow;
                    Ovt[vb]      = rna(v0);
                    Ovt[vb + L_] = rna(v1);
                }
            }
    }
}

// Output projection (same mainloop, fp32 [M,D] epilogue).
__global__ __launch_bounds__(256, 2)
void out_gemm(const float* __restrict__ A, const float* __restrict__ Bt,
              const float* __restrict__ bias, float* __restrict__ C)
{
    extern __shared__ char dsm[];
    const uint32_t raw  = smem_to_u32(dsm);
    const uint32_t base = (raw + 1023) & ~1023u;
    const int m0 = blockIdx.y * 128;
    const int n0 = blockIdx.x * 128;

    float acc[4][4][4];
    gemm_main128<false>(A, Bt, m0, n0, base, acc);

    const int lane = threadIdx.x & 31;
    const int wid  = threadIdx.x >> 5;
    const int wm = wid & 1, wn = wid >> 1;
    const int grp = lane >> 2;
    const int tig = lane & 3;
#pragma unroll
    for (int nt = 0; nt < 4; nt++) {
        const int col = n0 + wn * 32 + nt * 8 + tig * 2;
        const float b0 = bias[col], b1 = bias[col + 1];
#pragma unroll
        for (int mi = 0; mi < 4; mi++)
#pragma unroll
            for (int half = 0; half < 2; half++) {
                const int m = m0 + wm * 64 + mi * 16 + grp + half * 8;
                float2 v;
                v.x = acc[mi][nt][half * 2 + 0] + b0;
                v.y = acc[mi][nt][half * 2 + 1] + b1;
                *(float2*)(C + (size_t)m * D_ + col) = v;
            }
    }
}

// ---------------------------------------------------------------------------
// tf32 flash attention (R15-proven config): wide warp tile (32q x 64kv),
// CTA = 256 q, 8 warps, Q read from smem per ks, 4-stage ring, ONE
// sync/iter. NO P round-trip (K kv-permuted). Single change vs R15:
// exp interleaved with PV per kc (register-neutral; same FP order per
// accumulator -> bit-identical results).
// ---------------------------------------------------------------------------
#define AT_Q    0
#define AT_STG  65536
#define AT_SSZ  32768
#define AT_VOFF 16384
#define AT_DYN  (AT_STG + 4 * AT_SSZ + 1024)   // 197632

__global__ __launch_bounds__(256)
void attn_tf32(const float* __restrict__ Q, const float* __restrict__ K,
               const float* __restrict__ VT, float* __restrict__ O)
{
    extern __shared__ char dsm[];
    const uint32_t raw  = smem_to_u32(dsm);
    const uint32_t base = (raw + 1023) & ~1023u;

    const int tid = threadIdx.x;
    const int wid = tid >> 5;
    const int lane = tid & 31;
    const int b = blockIdx.z, h = blockIdx.y;
    const int q0 = blockIdx.x * 256;
    const size_t hoff = (size_t)(b * H_ + h) * L_ * HD_;

    // Q load: 256 rows x 256B (each thread: 1 row, 16 chunks)
    {
        const float* g = Q + hoff + (size_t)(q0 + tid) * HD_;
#pragma unroll
        for (int c = 0; c < 16; c++)
            CP_ASYNC16(base + AT_Q + SW256(tid, c * 16), g + c * 4);
    }
    const int sr = tid >> 2, scb0 = (tid & 3) * 64;
    auto load_stage = [&](int kt, int stg) {
        const uint32_t sb = base + AT_STG + (uint32_t)stg * AT_SSZ;
        const float* gk = K  + hoff + (size_t)(kt + sr) * HD_ + (scb0 >> 2);
        const float* gv = VT + hoff + (size_t)sr * L_ + kt + (scb0 >> 2);
#pragma unroll
        for (int c = 0; c < 4; c++) {
            const uint32_t so = SW256(sr, scb0 + c * 16);
            CP_ASYNC16(sb + so,           gk + c * 4);
            CP_ASYNC16(sb + AT_VOFF + so, gv + c * 4);
        }
    };
    load_stage(0, 0);   CP_COMMIT();   // g0: Q + stage0
    load_stage(64, 1);  CP_COMMIT();   // g1: stage1
    load_stage(128, 2); CP_COMMIT();   // g2: stage2
    CP_WAIT(2);
    __syncthreads();

    const int ar = (lane & 7) + ((lane >> 3) & 1) * 8;
    const int ac = (lane >> 4) * 16;
    const int br = (lane & 7) + ((lane >> 4) & 1) * 8;
    const int bc = ((lane >> 3) & 1) * 16;

    float oacc[2][8][4];
#pragma unroll
    for (int qi = 0; qi < 2; qi++)
#pragma unroll
        for (int nt = 0; nt < 8; nt++)
#pragma unroll
            for (int c = 0; c < 4; c++) oacc[qi][nt][c] = 0.0f;
    float lsum[2][2] = {{0.0f, 0.0f}, {0.0f, 0.0f}};

    const uint32_t qrow0 = (uint32_t)(wid * 32);

    const int NIT = L_ / 64;   // 32
    int scomp = 0;
    for (int it = 0; it < NIT; it++) {
        const uint32_t sb = base + AT_STG + (uint32_t)scomp * AT_SSZ;

        // ---- S = Q K^T (K kv-permuted) ----
        float sacc[2][8][4];
#pragma unroll
        for (int qi = 0; qi < 2; qi++)
#pragma unroll
            for (int nt = 0; nt < 8; nt++)
#pragma unroll
                for (int c = 0; c < 4; c++) sacc[qi][nt][c] = 0.0f;
#pragma unroll
        for (int ks = 0; ks < 8; ks++) {
            uint32_t qa[2][4];
#pragma unroll
            for (int qi = 0; qi < 2; qi++)
                ldsm_x4(base + AT_Q + SW256(qrow0 + qi * 16 + ar, ks * 32 + ac), qa[qi]);
            uint32_t kf[4][4];
#pragma unroll
            for (int nbh = 0; nbh < 4; nbh++)
                ldsm_x4(sb + SW256(nbh * 16 + br, ks * 32 + bc), kf[nbh]);
#pragma unroll
            for (int qi = 0; qi < 2; qi++)
#pragma unroll
                for (int nt = 0; nt < 8; nt++)
                    mma_tf32(sacc[qi][nt], qa[qi],
                             kf[nt >> 1][(nt & 1) * 2], kf[nt >> 1][(nt & 1) * 2 + 1]);
        }

        // ---- per kc: exp 8 values then that kc's PV MMAs (interleaved;
        //      register-neutral, same per-accumulator FP order) ----
#pragma unroll
        for (int kc = 0; kc < 8; kc++) {
            uint32_t vf[4][4];
#pragma unroll
            for (int nbh = 0; nbh < 4; nbh++)
                ldsm_x4(sb + AT_VOFF + SW256(nbh * 16 + br, kc * 32 + bc), vf[nbh]);
#pragma unroll
            for (int qi = 0; qi < 2; qi++) {
                const float t0 = trunc_tf32(__expf(sacc[qi][kc][0]));
                const float t1 = trunc_tf32(__expf(sacc[qi][kc][1]));
                const float t2 = trunc_tf32(__expf(sacc[qi][kc][2]));
                const float t3 = trunc_tf32(__expf(sacc[qi][kc][3]));
                lsum[qi][0] += t0 + t1;
                lsum[qi][1] += t2 + t3;
                const uint32_t pa[4] = {
                    __float_as_uint(t0), __float_as_uint(t2),
                    __float_as_uint(t1), __float_as_uint(t3) };
#pragma unroll
                for (int nt = 0; nt < 8; nt++)
                    mma_tf32(oacc[qi][nt], pa,
                             vf[nt >> 1][(nt & 1) * 2], vf[nt >> 1][(nt & 1) * 2 + 1]);
            }
        }

        // ---- pipeline: prefetch it+3 into (scomp+3)%4; wait for it+1 ----
        if (it + 3 < NIT) {
            int snext = scomp + 3; if (snext >= 4) snext -= 4;
            load_stage((it + 3) * 64, snext);
            CP_COMMIT();
        }
        if (it + 1 < NIT) {
            if (it + 3 < NIT)      { CP_WAIT(2); }
            else if (it + 2 < NIT) { CP_WAIT(1); }
            else                   { CP_WAIT(0); }
            __syncthreads();
        }
        if (++scomp == 4) scomp = 0;
    }

    // ---- epilogue ----
#pragma unroll
    for (int qi = 0; qi < 2; qi++)
#pragma unroll
        for (int hf = 0; hf < 2; hf++) {
            float s = lsum[qi][hf];
            s += __shfl_xor_sync(0xffffffffu, s, 1);
            s += __shfl_xor_sync(0xffffffffu, s, 2);
            lsum[qi][hf] = 1.0f / s;
        }

#pragma unroll
    for (int qi = 0; qi < 2; qi++) {
        const size_t row0 = (size_t)b * L_ + q0 + wid * 32 + qi * 16 + (lane >> 2);
        const size_t row1 = row0 + 8;
        const float inv0 = lsum[qi][0];
        const float inv1 = lsum[qi][1];
#pragma unroll
        for (int nt = 0; nt < 8; nt++) {
            const int col = h * HD_ + nt * 8 + (lane & 3) * 2;
            float2 v0; v0.x = rna(oacc[qi][nt][0] * inv0); v0.y = rna(oacc[qi][nt][1] * inv0);
            float2 v1; v1.x = rna(oacc[qi][nt][2] * inv1); v1.y = rna(oacc[qi][nt][3] * inv1);
            *(float2*)(O + row0 * D_ + col) = v0;
            *(float2*)(O + row1 * D_ + col) = v1;
        }
    }
}

// ---------------------------------------------------------------------------
extern "C" void kernel_launch(void* const* d_in, const int* in_sizes, int n_in,
                              void* d_out, int out_size)
{
    const float* x  = (const float*)d_in[0];
    const float* Wq = (const float*)d_in[1];
    const float* bq = (const float*)d_in[2];
    const float* Wk = (const float*)d_in[3];
    const float* bk = (const float*)d_in[4];
    const float* Wv = (const float*)d_in[5];
    const float* bv = (const float*)d_in[6];
    const float* Wo = (const float*)d_in[7];
    const float* bo = (const float*)d_in[8];
    float* out = (float*)d_out;

    float *q, *k, *vt, *o, *wt;
    cudaGetSymbolAddress((void**)&q,  g_q);
    cudaGetSymbolAddress((void**)&k,  g_k);
    cudaGetSymbolAddress((void**)&vt, g_vt);
    cudaGetSymbolAddress((void**)&o,  g_o);
    cudaGetSymbolAddress((void**)&wt, g_wt);
    const size_t WSZ = (size_t)D_ * D_;

    cudaFuncSetAttribute(qkv_gemm,  cudaFuncAttributeMaxDynamicSharedMemorySize, G_DYN);
    cudaFuncSetAttribute(out_gemm,  cudaFuncAttributeMaxDynamicSharedMemorySize, G_DYN);
    cudaFuncSetAttribute(attn_tf32, cudaFuncAttributeMaxDynamicSharedMemorySize, AT_DYN);

    // 1. weight transpose + round
    pre_w<<<dim3(D_ / 32, D_ / 32, 4), 256>>>(Wq, Wk, Wv, Wo, wt);

    // 2. fused QKV projections (128x128 tiles, K32, 3-stage, 2 CTAs/SM)
    qkv_gemm<<<dim3(D_ / 128, M_ / 128, 3), 256, G_DYN>>>(
        x, wt, bq, bk, bv, q, k, vt);

    // 3. attention (R15 config + interleaved exp/PV)
    attn_tf32<<<dim3(L_ / 256, H_, B_), 256, AT_DYN>>>(q, k, vt, o);

    // 4. output projection (K32, 3-stage, 2 CTAs/SM)
    out_gemm<<<dim3(D_ / 128, M_ / 128), 256, G_DYN>>>(o, wt + 3 * WSZ, bo, out);
}